// round 1
// baseline (speedup 1.0000x reference)
#include <cuda_runtime.h>
#include <math.h>

#define Bn 512
#define Cn 1000
#define Dn 512
#define Kn 10

// Scratch (device globals — no allocations allowed)
__device__ float g_W[Cn * Dn];     // softmax weights
__device__ float g_WP[Cn * Dn];    // -2 * w * proto
__device__ float g_Cc[Cn];         // sum_d w * p^2
__device__ float g_simi[Bn * Cn];  // distances

// ---------------------------------------------------------------------------
// Kernel 1: per-class weight prep. 1 block per class, 128 threads, 4 d/thread.
// rd = sqrt(N*ex2^2 - ex1^2); w = softmax over d of (rowmax - rd)
//   softmax(m - rd)_d == exp(rdmin - rd_d) / sum_d exp(rdmin - rd_d)
// ---------------------------------------------------------------------------
__global__ void prep_kernel(const float* __restrict__ protos,
                            const float* __restrict__ ex2,
                            const float* __restrict__ ex1,
                            const int*   __restrict__ cls_num) {
    const int c = blockIdx.x;
    const int t = threadIdx.x;  // 128 threads
    const float N = (float)cls_num[c];

    float rd[4];
    float mn = INFINITY;
#pragma unroll
    for (int i = 0; i < 4; i++) {
        int d = t + i * 128;
        float e2 = ex2[c * Dn + d];
        float e1 = ex1[c * Dn + d];
        float v = sqrtf(N * e2 * e2 - e1 * e1);
        rd[i] = v;
        mn = fminf(mn, v);
    }

    __shared__ float sred[128];
    // block-min
    sred[t] = mn;
    __syncthreads();
    for (int s = 64; s > 0; s >>= 1) {
        if (t < s) sred[t] = fminf(sred[t], sred[t + s]);
        __syncthreads();
    }
    mn = sred[0];
    __syncthreads();

    float e[4];
    float lsum = 0.f;
#pragma unroll
    for (int i = 0; i < 4; i++) {
        e[i] = expf(mn - rd[i]);
        lsum += e[i];
    }
    // block-sum
    sred[t] = lsum;
    __syncthreads();
    for (int s = 64; s > 0; s >>= 1) {
        if (t < s) sred[t] += sred[t + s];
        __syncthreads();
    }
    const float inv = 1.0f / sred[0];
    __syncthreads();

    float csum = 0.f;
#pragma unroll
    for (int i = 0; i < 4; i++) {
        int d = t + i * 128;
        float w = e[i] * inv;
        float p = protos[c * Dn + d];
        g_W[c * Dn + d]  = w;
        g_WP[c * Dn + d] = -2.0f * w * p;
        csum += w * p * p;
    }
    // block-sum csum
    sred[t] = csum;
    __syncthreads();
    for (int s = 64; s > 0; s >>= 1) {
        if (t < s) sred[t] += sred[t + s];
        __syncthreads();
    }
    if (t == 0) g_Cc[c] = sred[0];
}

// ---------------------------------------------------------------------------
// Kernel 2: dual GEMM  simi[b,c] = sum_k x^2*W + x*WP  (+ Cc[c])
// 64x64 tile, BK=16, 256 threads, 4x4 microtile.
// ---------------------------------------------------------------------------
#define BM 64
#define BN 64
#define BK 16

__global__ __launch_bounds__(256) void gemm_kernel(const float* __restrict__ x) {
    __shared__ float Xs [BK][BM];
    __shared__ float X2s[BK][BM];
    __shared__ float Ws [BK][BN];
    __shared__ float WPs[BK][BN];

    const int tx = threadIdx.x & 15;   // 0..15  -> c microtile
    const int ty = threadIdx.x >> 4;   // 0..15  -> b microtile
    const int c0 = blockIdx.x * BN;
    const int b0 = blockIdx.y * BM;

    float acc[4][4] = {};

    for (int k0 = 0; k0 < Dn; k0 += BK) {
        // Load tiles: 1024 elems per array, 4 per thread.
#pragma unroll
        for (int l = 0; l < 4; l++) {
            int idx = threadIdx.x + l * 256;
            int row = idx >> 4;
            int kk  = idx & 15;
            float xv = x[(b0 + row) * Dn + k0 + kk];
            Xs [kk][row] = xv;
            X2s[kk][row] = xv * xv;
            int c = c0 + row;
            float wv = 0.f, wpv = 0.f;
            if (c < Cn) {
                wv  = g_W [c * Dn + k0 + kk];
                wpv = g_WP[c * Dn + k0 + kk];
            }
            Ws [kk][row] = wv;
            WPs[kk][row] = wpv;
        }
        __syncthreads();

#pragma unroll
        for (int kk = 0; kk < BK; kk++) {
            float4 a  = *reinterpret_cast<const float4*>(&Xs [kk][ty * 4]);
            float4 a2 = *reinterpret_cast<const float4*>(&X2s[kk][ty * 4]);
            float4 bw = *reinterpret_cast<const float4*>(&Ws [kk][tx * 4]);
            float4 bp = *reinterpret_cast<const float4*>(&WPs[kk][tx * 4]);
            const float av[4]  = {a.x,  a.y,  a.z,  a.w};
            const float a2v[4] = {a2.x, a2.y, a2.z, a2.w};
            const float bwv[4] = {bw.x, bw.y, bw.z, bw.w};
            const float bpv[4] = {bp.x, bp.y, bp.z, bp.w};
#pragma unroll
            for (int i = 0; i < 4; i++)
#pragma unroll
                for (int j = 0; j < 4; j++)
                    acc[i][j] += a2v[i] * bwv[j] + av[i] * bpv[j];
        }
        __syncthreads();
    }

#pragma unroll
    for (int i = 0; i < 4; i++) {
        int b = b0 + ty * 4 + i;
#pragma unroll
        for (int j = 0; j < 4; j++) {
            int c = c0 + tx * 4 + j;
            if (c < Cn) g_simi[b * Cn + c] = acc[i][j] + g_Cc[c];
        }
    }
}

// ---------------------------------------------------------------------------
// Kernel 3: top-10 smallest per row (iterative masked argmin), confidence,
// argmax, label lookup. 1 block (256 thr) per row.
// Output layout: out[0..B)   = predict (float-cast labels)
//                out[B + b*K + k] = topk_conf
// ---------------------------------------------------------------------------
__global__ void topk_kernel(const int* __restrict__ proto_label,
                            float* __restrict__ out) {
    const int b = blockIdx.x;
    const int t = threadIdx.x;  // 256

    __shared__ float svals[Cn];
    __shared__ float rv[256];
    __shared__ int   ri[256];
    __shared__ float topv[Kn];
    __shared__ int   topi[Kn];

    for (int c = t; c < Cn; c += 256) svals[c] = g_simi[b * Cn + c];
    __syncthreads();

    for (int k = 0; k < Kn; k++) {
        float bv = INFINITY;
        int   bi = Cn;
        for (int c = t; c < Cn; c += 256) {
            float v = svals[c];
            if (v < bv) { bv = v; bi = c; }
        }
        rv[t] = bv; ri[t] = bi;
        __syncthreads();
        for (int s = 128; s > 0; s >>= 1) {
            if (t < s) {
                if (rv[t + s] < rv[t] ||
                    (rv[t + s] == rv[t] && ri[t + s] < ri[t])) {
                    rv[t] = rv[t + s];
                    ri[t] = ri[t + s];
                }
            }
            __syncthreads();
        }
        if (t == 0) {
            topv[k] = rv[0];
            topi[k] = ri[0];
            svals[ri[0]] = INFINITY;  // mask selected
        }
        __syncthreads();
    }

    if (t == 0) {
        float S = 0.f;
#pragma unroll
        for (int k = 0; k < Kn; k++) S += topv[k];
        float bestc = -INFINITY;
        int bestk = 0;
#pragma unroll
        for (int k = 0; k < Kn; k++) {
            float conf = S / topv[k];
            out[Bn + b * Kn + k] = conf;
            if (conf > bestc) { bestc = conf; bestk = k; }
        }
        out[b] = (float)proto_label[topi[bestk]];
    }
}

// ---------------------------------------------------------------------------
extern "C" void kernel_launch(void* const* d_in, const int* in_sizes, int n_in,
                              void* d_out, int out_size) {
    const float* x           = (const float*)d_in[0];
    const float* protos      = (const float*)d_in[1];
    const float* ex2         = (const float*)d_in[2];
    const float* ex1         = (const float*)d_in[3];
    const int*   cls_num     = (const int*)d_in[4];
    const int*   proto_label = (const int*)d_in[5];
    float* out = (float*)d_out;

    prep_kernel<<<Cn, 128>>>(protos, ex2, ex1, cls_num);
    dim3 grid((Cn + BN - 1) / BN, Bn / BM);
    gemm_kernel<<<grid, 256>>>(x);
    topk_kernel<<<Bn, 256>>>(proto_label, out);
}

// round 2
// speedup vs baseline: 1.0610x; 1.0610x over previous
#include <cuda_runtime.h>
#include <math.h>

#define Bn 512
#define Cn 1000
#define CP 1024   // padded class count (device globals are zero-initialized)
#define Dn 512
#define Kn 10

// Scratch (device globals — no allocations allowed)
__device__ float g_W [CP * Dn];    // softmax weights (rows >= Cn stay zero)
__device__ float g_WP[CP * Dn];    // -2 * w * proto
__device__ float g_Cc[CP];         // sum_d w * p^2
__device__ float g_simi[Bn * Cn];  // distances

// ---------------------------------------------------------------------------
// Kernel 1: per-class weight prep. 1 block per class, 128 threads, 4 d/thread
// (consecutive, float4). Warp shuffles + tiny smem for cross-warp reduce.
// ---------------------------------------------------------------------------
__global__ void prep_kernel(const float* __restrict__ protos,
                            const float* __restrict__ ex2,
                            const float* __restrict__ ex1,
                            const int*   __restrict__ cls_num) {
    const int c = blockIdx.x;
    const int t = threadIdx.x;          // 128
    const int wid = t >> 5, lane = t & 31;
    const float N = (float)cls_num[c];

    const float4 e2 = *reinterpret_cast<const float4*>(ex2 + c * Dn + t * 4);
    const float4 e1 = *reinterpret_cast<const float4*>(ex1 + c * Dn + t * 4);

    float rd[4];
    rd[0] = sqrtf(N * e2.x * e2.x - e1.x * e1.x);
    rd[1] = sqrtf(N * e2.y * e2.y - e1.y * e1.y);
    rd[2] = sqrtf(N * e2.z * e2.z - e1.z * e1.z);
    rd[3] = sqrtf(N * e2.w * e2.w - e1.w * e1.w);

    float mn = fminf(fminf(rd[0], rd[1]), fminf(rd[2], rd[3]));
#pragma unroll
    for (int off = 16; off; off >>= 1)
        mn = fminf(mn, __shfl_xor_sync(0xffffffffu, mn, off));

    __shared__ float sm[4];
    __shared__ float ss[4];
    if (lane == 0) sm[wid] = mn;
    __syncthreads();
    mn = fminf(fminf(sm[0], sm[1]), fminf(sm[2], sm[3]));

    float e[4], lsum = 0.f;
#pragma unroll
    for (int i = 0; i < 4; i++) { e[i] = __expf(mn - rd[i]); lsum += e[i]; }
#pragma unroll
    for (int off = 16; off; off >>= 1)
        lsum += __shfl_xor_sync(0xffffffffu, lsum, off);
    if (lane == 0) ss[wid] = lsum;
    __syncthreads();
    const float inv = 1.0f / (ss[0] + ss[1] + ss[2] + ss[3]);

    const float4 p = *reinterpret_cast<const float4*>(protos + c * Dn + t * 4);
    const float pv[4] = {p.x, p.y, p.z, p.w};
    float4 wv, wpv;
    float* wvp = &wv.x; float* wppv = &wpv.x;
    float csum = 0.f;
#pragma unroll
    for (int i = 0; i < 4; i++) {
        float w = e[i] * inv;
        wvp[i]  = w;
        wppv[i] = -2.0f * w * pv[i];
        csum += w * pv[i] * pv[i];
    }
    *reinterpret_cast<float4*>(g_W  + c * Dn + t * 4) = wv;
    *reinterpret_cast<float4*>(g_WP + c * Dn + t * 4) = wpv;

#pragma unroll
    for (int off = 16; off; off >>= 1)
        csum += __shfl_xor_sync(0xffffffffu, csum, off);
    if (lane == 0) ss[wid] = csum;   // reuse after barrier below
    __syncthreads();
    if (t == 0) g_Cc[c] = ss[0] + ss[1] + ss[2] + ss[3];
}

// ---------------------------------------------------------------------------
// Kernel 2: dual GEMM  simi[b,c] = sum_k (x^2*W + x*WP) + Cc[c]
// 64x64 tile, BK=16, 256 threads, 4x4 microtile, register-prefetch pipeline.
// ---------------------------------------------------------------------------
#define BM 64
#define BN 64
#define BK 16
#define PAD 4
#define LDW (BM + PAD)   // 68 floats: 16B-aligned stride, conflict-free stores

__global__ __launch_bounds__(256, 1) void gemm_kernel(const float* __restrict__ x) {
    __shared__ float Xs [BK][LDW];
    __shared__ float X2s[BK][LDW];
    __shared__ float Ws [BK][LDW];
    __shared__ float WPs[BK][LDW];

    const int tx = threadIdx.x & 15;   // c microtile
    const int ty = threadIdx.x >> 4;   // b microtile
    const int c0 = blockIdx.x * BN;    // < 1024 (padded scratch: no bounds check)
    const int b0 = blockIdx.y * BM;

    const int row = threadIdx.x >> 2;  // 0..63
    const int seg = threadIdx.x & 3;   // 0..3  (k sub-segment, 4 floats)

    const float* xp  = x    + (b0 + row) * Dn + seg * 4;
    const float* wp  = g_W  + (c0 + row) * Dn + seg * 4;
    const float* wpp = g_WP + (c0 + row) * Dn + seg * 4;

    float4 cx  = *reinterpret_cast<const float4*>(xp);
    float4 cw  = *reinterpret_cast<const float4*>(wp);
    float4 cwp = *reinterpret_cast<const float4*>(wpp);

    float acc[4][4] = {};

    for (int kt = 0; kt < Dn / BK; kt++) {
        // stage current tile into smem
        const float xv[4]  = {cx.x, cx.y, cx.z, cx.w};
        const float wv[4]  = {cw.x, cw.y, cw.z, cw.w};
        const float wpv[4] = {cwp.x, cwp.y, cwp.z, cwp.w};
#pragma unroll
        for (int i = 0; i < 4; i++) {
            const int kk = seg * 4 + i;
            Xs [kk][row] = xv[i];
            X2s[kk][row] = xv[i] * xv[i];
            Ws [kk][row] = wv[i];
            WPs[kk][row] = wpv[i];
        }
        __syncthreads();

        // prefetch next tile (latency hidden by compute below)
        if (kt + 1 < Dn / BK) {
            const int koff = (kt + 1) * BK;
            cx  = *reinterpret_cast<const float4*>(xp  + koff);
            cw  = *reinterpret_cast<const float4*>(wp  + koff);
            cwp = *reinterpret_cast<const float4*>(wpp + koff);
        }

#pragma unroll
        for (int kk = 0; kk < BK; kk++) {
            float4 a  = *reinterpret_cast<const float4*>(&Xs [kk][ty * 4]);
            float4 a2 = *reinterpret_cast<const float4*>(&X2s[kk][ty * 4]);
            float4 bw = *reinterpret_cast<const float4*>(&Ws [kk][tx * 4]);
            float4 bp = *reinterpret_cast<const float4*>(&WPs[kk][tx * 4]);
            const float av[4]  = {a.x,  a.y,  a.z,  a.w};
            const float a2v[4] = {a2.x, a2.y, a2.z, a2.w};
            const float bwv[4] = {bw.x, bw.y, bw.z, bw.w};
            const float bpv[4] = {bp.x, bp.y, bp.z, bp.w};
#pragma unroll
            for (int i = 0; i < 4; i++)
#pragma unroll
                for (int j = 0; j < 4; j++)
                    acc[i][j] += a2v[i] * bwv[j] + av[i] * bpv[j];
        }
        __syncthreads();
    }

#pragma unroll
    for (int i = 0; i < 4; i++) {
        const int b = b0 + ty * 4 + i;
#pragma unroll
        for (int j = 0; j < 4; j++) {
            const int c = c0 + tx * 4 + j;
            if (c < Cn) g_simi[b * Cn + c] = acc[i][j] + g_Cc[c];
        }
    }
}

// ---------------------------------------------------------------------------
// Kernel 3: one WARP per row. Per-lane register top-10 (insertion), then
// 10 rounds of warp-shuffle argmin merge. Tie-break: lower index (matches
// jax.lax.top_k stability).
// Output: out[0..B) = predict (float labels), out[B + b*K + k] = conf.
// ---------------------------------------------------------------------------
__global__ void topk_kernel(const int* __restrict__ proto_label,
                            float* __restrict__ out) {
    const int warp = threadIdx.x >> 5;
    const int lane = threadIdx.x & 31;
    const int r = blockIdx.x * 8 + warp;   // row (blockDim 256 = 8 warps)
    if (r >= Bn) return;

    float tv[Kn]; int tix[Kn];
#pragma unroll
    for (int i = 0; i < Kn; i++) { tv[i] = INFINITY; tix[i] = 0x7fffffff; }

    const float* srow = g_simi + r * Cn;
    for (int c = lane; c < Cn; c += 32) {
        float v = srow[c];
        if (v < tv[Kn - 1]) {
            float cv = v; int ci = c;
#pragma unroll
            for (int i = 0; i < Kn; i++) {
                if (cv < tv[i]) {
                    float fv = tv[i]; tv[i] = cv; cv = fv;
                    int   fi = tix[i]; tix[i] = ci; ci = fi;
                }
            }
        }
    }

    float sel_v[Kn]; int sel_i[Kn];
#pragma unroll
    for (int k = 0; k < Kn; k++) {
        float v = tv[0]; int idx = tix[0];
#pragma unroll
        for (int off = 16; off; off >>= 1) {
            float ov = __shfl_down_sync(0xffffffffu, v, off);
            int   oi = __shfl_down_sync(0xffffffffu, idx, off);
            if (ov < v || (ov == v && oi < idx)) { v = ov; idx = oi; }
        }
        v   = __shfl_sync(0xffffffffu, v, 0);
        idx = __shfl_sync(0xffffffffu, idx, 0);
        sel_v[k] = v; sel_i[k] = idx;
        if (tix[0] == idx) {   // winning lane pops its head
#pragma unroll
            for (int i = 0; i < Kn - 1; i++) { tv[i] = tv[i + 1]; tix[i] = tix[i + 1]; }
            tv[Kn - 1] = INFINITY; tix[Kn - 1] = 0x7fffffff;
        }
    }

    if (lane == 0) {
        float S = 0.f;
#pragma unroll
        for (int k = 0; k < Kn; k++) S += sel_v[k];
        float bestc = -INFINITY; int bestk = 0;
#pragma unroll
        for (int k = 0; k < Kn; k++) {
            float conf = S / sel_v[k];
            out[Bn + r * Kn + k] = conf;
            if (conf > bestc) { bestc = conf; bestk = k; }
        }
        out[r] = (float)proto_label[sel_i[bestk]];
    }
}

// ---------------------------------------------------------------------------
extern "C" void kernel_launch(void* const* d_in, const int* in_sizes, int n_in,
                              void* d_out, int out_size) {
    const float* x           = (const float*)d_in[0];
    const float* protos      = (const float*)d_in[1];
    const float* ex2         = (const float*)d_in[2];
    const float* ex1         = (const float*)d_in[3];
    const int*   cls_num     = (const int*)d_in[4];
    const int*   proto_label = (const int*)d_in[5];
    float* out = (float*)d_out;

    prep_kernel<<<Cn, 128>>>(protos, ex2, ex1, cls_num);
    dim3 grid(CP / BN, Bn / BM);   // 16 x 8 = 128 blocks
    gemm_kernel<<<grid, 256>>>(x);
    topk_kernel<<<Bn / 8, 256>>>(proto_label, out);
}

// round 3
// speedup vs baseline: 1.8061x; 1.7022x over previous
#include <cuda_runtime.h>
#include <math.h>

#define Bn 512
#define Cn 1000
#define CP 1024   // padded class count (device globals zero-initialized)
#define Dn 512
#define Kn 10

// Scratch (device globals — no allocations allowed)
__device__ float g_W [CP * Dn];        // softmax weights (rows >= Cn stay zero)
__device__ float g_WP[CP * Dn];        // -2 * w * proto
__device__ float g_Cc[CP];             // sum_d w * p^2
__device__ float g_simiP[2 * Bn * Cn]; // K-split partial distances

// ---------------------------------------------------------------------------
// packed f32x2 helpers
// ---------------------------------------------------------------------------
__device__ __forceinline__ unsigned long long dup2(float v) {
    unsigned long long r;
    asm("mov.b64 %0, {%1, %1};" : "=l"(r) : "r"(__float_as_uint(v)));
    return r;
}
__device__ __forceinline__ void fma2(unsigned long long& acc,
                                     unsigned long long a,
                                     unsigned long long b) {
    asm("fma.rn.f32x2 %0, %1, %2, %0;" : "+l"(acc) : "l"(a), "l"(b));
}
__device__ __forceinline__ float lo32(unsigned long long v) {
    return __uint_as_float((unsigned)(v & 0xffffffffull));
}
__device__ __forceinline__ float hi32(unsigned long long v) {
    return __uint_as_float((unsigned)(v >> 32));
}

// ---------------------------------------------------------------------------
// Kernel 1: per-class weight prep (MUFU-floor bound, ~7.5us)
// ---------------------------------------------------------------------------
__global__ void prep_kernel(const float* __restrict__ protos,
                            const float* __restrict__ ex2,
                            const float* __restrict__ ex1,
                            const int*   __restrict__ cls_num) {
    const int c = blockIdx.x;
    const int t = threadIdx.x;          // 128
    const int wid = t >> 5, lane = t & 31;
    const float N = (float)cls_num[c];

    const float4 e2 = *reinterpret_cast<const float4*>(ex2 + c * Dn + t * 4);
    const float4 e1 = *reinterpret_cast<const float4*>(ex1 + c * Dn + t * 4);

    float rd[4];
    rd[0] = sqrtf(N * e2.x * e2.x - e1.x * e1.x);
    rd[1] = sqrtf(N * e2.y * e2.y - e1.y * e1.y);
    rd[2] = sqrtf(N * e2.z * e2.z - e1.z * e1.z);
    rd[3] = sqrtf(N * e2.w * e2.w - e1.w * e1.w);

    float mn = fminf(fminf(rd[0], rd[1]), fminf(rd[2], rd[3]));
#pragma unroll
    for (int off = 16; off; off >>= 1)
        mn = fminf(mn, __shfl_xor_sync(0xffffffffu, mn, off));

    __shared__ float sm[4];
    __shared__ float ss[4];
    if (lane == 0) sm[wid] = mn;
    __syncthreads();
    mn = fminf(fminf(sm[0], sm[1]), fminf(sm[2], sm[3]));

    float e[4], lsum = 0.f;
#pragma unroll
    for (int i = 0; i < 4; i++) { e[i] = __expf(mn - rd[i]); lsum += e[i]; }
#pragma unroll
    for (int off = 16; off; off >>= 1)
        lsum += __shfl_xor_sync(0xffffffffu, lsum, off);
    if (lane == 0) ss[wid] = lsum;
    __syncthreads();
    const float inv = 1.0f / (ss[0] + ss[1] + ss[2] + ss[3]);

    const float4 p = *reinterpret_cast<const float4*>(protos + c * Dn + t * 4);
    const float pv[4] = {p.x, p.y, p.z, p.w};
    float4 wv, wpv;
    float* wvp = &wv.x; float* wppv = &wpv.x;
    float csum = 0.f;
#pragma unroll
    for (int i = 0; i < 4; i++) {
        float w = e[i] * inv;
        wvp[i]  = w;
        wppv[i] = -2.0f * w * pv[i];
        csum += w * pv[i] * pv[i];
    }
    *reinterpret_cast<float4*>(g_W  + c * Dn + t * 4) = wv;
    *reinterpret_cast<float4*>(g_WP + c * Dn + t * 4) = wpv;

#pragma unroll
    for (int off = 16; off; off >>= 1)
        csum += __shfl_xor_sync(0xffffffffu, csum, off);
    __syncthreads();            // protect ss reuse
    if (lane == 0) ss[wid] = csum;
    __syncthreads();
    if (t == 0) g_Cc[c] = ss[0] + ss[1] + ss[2] + ss[3];
}

// ---------------------------------------------------------------------------
// Kernel 2: dual GEMM via packed fma.rn.f32x2, K-split x2.
//   simiP[z][b,c] = sum_{k in half z} (x^2*W + x*WP)
// 64x64 tile, BK=16, 256 threads, 4x4 microtile (8 packed accumulators).
// ---------------------------------------------------------------------------
#define BM 64
#define BN 64
#define BK 16
#define LDW 68   // 16B-aligned stride (68*4=272), conflict-free LDS.128

__global__ __launch_bounds__(256) void gemm_kernel(const float* __restrict__ x) {
    __shared__ float Xs [BK][LDW];
    __shared__ float X2s[BK][LDW];
    __shared__ float Ws [BK][LDW];
    __shared__ float WPs[BK][LDW];

    const int tx = threadIdx.x & 15;   // c microtile
    const int ty = threadIdx.x >> 4;   // b microtile
    const int c0 = blockIdx.x * BN;    // padded scratch: no bounds check on loads
    const int b0 = blockIdx.y * BM;
    const int kbase = blockIdx.z * (Dn / 2);

    const int row = threadIdx.x >> 2;  // 0..63
    const int seg = threadIdx.x & 3;   // 0..3

    const float* xp  = x    + (b0 + row) * Dn + kbase + seg * 4;
    const float* wp  = g_W  + (c0 + row) * Dn + kbase + seg * 4;
    const float* wpp = g_WP + (c0 + row) * Dn + kbase + seg * 4;

    float4 cx  = *reinterpret_cast<const float4*>(xp);
    float4 cw  = *reinterpret_cast<const float4*>(wp);
    float4 cwp = *reinterpret_cast<const float4*>(wpp);

    unsigned long long acc[4][2] = {};   // [i][j2], packed pair over j

    const int NT = (Dn / 2) / BK;        // 16 k-tiles
    for (int kt = 0; kt < NT; kt++) {
        const float xv[4]  = {cx.x, cx.y, cx.z, cx.w};
        const float wv[4]  = {cw.x, cw.y, cw.z, cw.w};
        const float wpv[4] = {cwp.x, cwp.y, cwp.z, cwp.w};
#pragma unroll
        for (int i = 0; i < 4; i++) {
            const int kk = seg * 4 + i;
            Xs [kk][row] = xv[i];
            X2s[kk][row] = xv[i] * xv[i];
            Ws [kk][row] = wv[i];
            WPs[kk][row] = wpv[i];
        }
        __syncthreads();

        if (kt + 1 < NT) {
            const int koff = (kt + 1) * BK;
            cx  = *reinterpret_cast<const float4*>(xp  + koff);
            cw  = *reinterpret_cast<const float4*>(wp  + koff);
            cwp = *reinterpret_cast<const float4*>(wpp + koff);
        }

#pragma unroll
        for (int kk = 0; kk < BK; kk++) {
            const float4 a  = *reinterpret_cast<const float4*>(&Xs [kk][ty * 4]);
            const float4 a2 = *reinterpret_cast<const float4*>(&X2s[kk][ty * 4]);
            const ulonglong2 bw = *reinterpret_cast<const ulonglong2*>(&Ws [kk][tx * 4]);
            const ulonglong2 bp = *reinterpret_cast<const ulonglong2*>(&WPs[kk][tx * 4]);

            const unsigned long long ad[4]  = {dup2(a.x),  dup2(a.y),  dup2(a.z),  dup2(a.w)};
            const unsigned long long a2d[4] = {dup2(a2.x), dup2(a2.y), dup2(a2.z), dup2(a2.w)};
#pragma unroll
            for (int i = 0; i < 4; i++) {
                fma2(acc[i][0], a2d[i], bw.x);
                fma2(acc[i][1], a2d[i], bw.y);
                fma2(acc[i][0], ad[i],  bp.x);
                fma2(acc[i][1], ad[i],  bp.y);
            }
        }
        __syncthreads();
    }

    float* outz = g_simiP + blockIdx.z * (Bn * Cn);
#pragma unroll
    for (int i = 0; i < 4; i++) {
        const int b = b0 + ty * 4 + i;
#pragma unroll
        for (int j2 = 0; j2 < 2; j2++) {
            const int c = c0 + tx * 4 + j2 * 2;
            if (c < Cn)     outz[b * Cn + c]     = lo32(acc[i][j2]);
            if (c + 1 < Cn) outz[b * Cn + c + 1] = hi32(acc[i][j2]);
        }
    }
}

// ---------------------------------------------------------------------------
// Kernel 3: one WARP per row. Sums the two K-split partials + Cc, per-lane
// register top-10 insertion, 10 warp-shuffle argmin merges.
// Output: out[0..B) = predict (float labels), out[B + b*K + k] = conf.
// ---------------------------------------------------------------------------
__global__ void topk_kernel(const int* __restrict__ proto_label,
                            float* __restrict__ out) {
    const int warp = threadIdx.x >> 5;
    const int lane = threadIdx.x & 31;
    const int r = blockIdx.x * 8 + warp;
    if (r >= Bn) return;

    float tv[Kn]; int tix[Kn];
#pragma unroll
    for (int i = 0; i < Kn; i++) { tv[i] = INFINITY; tix[i] = 0x7fffffff; }

    const float* sA = g_simiP + r * Cn;
    const float* sB = g_simiP + Bn * Cn + r * Cn;
    for (int c = lane; c < Cn; c += 32) {
        float v = sA[c] + sB[c] + g_Cc[c];
        if (v < tv[Kn - 1]) {
            float cv = v; int ci = c;
#pragma unroll
            for (int i = 0; i < Kn; i++) {
                if (cv < tv[i]) {
                    float fv = tv[i]; tv[i] = cv; cv = fv;
                    int   fi = tix[i]; tix[i] = ci; ci = fi;
                }
            }
        }
    }

    float sel_v[Kn]; int sel_i[Kn];
#pragma unroll
    for (int k = 0; k < Kn; k++) {
        float v = tv[0]; int idx = tix[0];
#pragma unroll
        for (int off = 16; off; off >>= 1) {
            float ov = __shfl_down_sync(0xffffffffu, v, off);
            int   oi = __shfl_down_sync(0xffffffffu, idx, off);
            if (ov < v || (ov == v && oi < idx)) { v = ov; idx = oi; }
        }
        v   = __shfl_sync(0xffffffffu, v, 0);
        idx = __shfl_sync(0xffffffffu, idx, 0);
        sel_v[k] = v; sel_i[k] = idx;
        if (tix[0] == idx) {
#pragma unroll
            for (int i = 0; i < Kn - 1; i++) { tv[i] = tv[i + 1]; tix[i] = tix[i + 1]; }
            tv[Kn - 1] = INFINITY; tix[Kn - 1] = 0x7fffffff;
        }
    }

    if (lane == 0) {
        float S = 0.f;
#pragma unroll
        for (int k = 0; k < Kn; k++) S += sel_v[k];
        float bestc = -INFINITY; int bestk = 0;
#pragma unroll
        for (int k = 0; k < Kn; k++) {
            float conf = S / sel_v[k];
            out[Bn + r * Kn + k] = conf;
            if (conf > bestc) { bestc = conf; bestk = k; }
        }
        out[r] = (float)proto_label[sel_i[bestk]];
    }
}

// ---------------------------------------------------------------------------
extern "C" void kernel_launch(void* const* d_in, const int* in_sizes, int n_in,
                              void* d_out, int out_size) {
    const float* x           = (const float*)d_in[0];
    const float* protos      = (const float*)d_in[1];
    const float* ex2         = (const float*)d_in[2];
    const float* ex1         = (const float*)d_in[3];
    const int*   cls_num     = (const int*)d_in[4];
    const int*   proto_label = (const int*)d_in[5];
    float* out = (float*)d_out;

    prep_kernel<<<Cn, 128>>>(protos, ex2, ex1, cls_num);
    dim3 grid(CP / BN, Bn / BM, 2);   // 16 x 8 x 2 = 256 blocks
    gemm_kernel<<<grid, 256>>>(x);
    topk_kernel<<<Bn / 8, 256>>>(proto_label, out);
}

// round 4
// speedup vs baseline: 2.0442x; 1.1318x over previous
#include <cuda_runtime.h>
#include <math.h>

#define Bn 512
#define Cn 1000
#define CP 1024   // padded class count (device globals zero-initialized)
#define Dn 512
#define Kn 10
#define ZS 4      // K-split factor

// Scratch (device globals — no allocations allowed)
__device__ float g_W [CP * Dn];          // softmax weights (rows >= Cn stay zero)
__device__ float g_WP[CP * Dn];          // -2 * w * proto
__device__ float g_Cc[CP];               // sum_d w * p^2
__device__ float g_simiP[ZS * Bn * Cn];  // K-split partial distances

// ---------------------------------------------------------------------------
// packed f32x2 helpers
// ---------------------------------------------------------------------------
__device__ __forceinline__ void fma2(unsigned long long& acc,
                                     unsigned long long a,
                                     unsigned long long b) {
    asm("fma.rn.f32x2 %0, %1, %2, %0;" : "+l"(acc) : "l"(a), "l"(b));
}
__device__ __forceinline__ float lo32(unsigned long long v) {
    return __uint_as_float((unsigned)(v & 0xffffffffull));
}
__device__ __forceinline__ float hi32(unsigned long long v) {
    return __uint_as_float((unsigned)(v >> 32));
}
__device__ __forceinline__ float fsqrt_approx(float v) {
    float r;
    asm("sqrt.approx.f32 %0, %1;" : "=f"(r) : "f"(v));
    return r;
}

// ---------------------------------------------------------------------------
// Kernel 1: per-class weight prep (MUFU-bound)
// ---------------------------------------------------------------------------
__global__ void prep_kernel(const float* __restrict__ protos,
                            const float* __restrict__ ex2,
                            const float* __restrict__ ex1,
                            const int*   __restrict__ cls_num) {
    const int c = blockIdx.x;
    const int t = threadIdx.x;          // 128
    const int wid = t >> 5, lane = t & 31;
    const float N = (float)cls_num[c];

    const float4 e2 = *reinterpret_cast<const float4*>(ex2 + c * Dn + t * 4);
    const float4 e1 = *reinterpret_cast<const float4*>(ex1 + c * Dn + t * 4);

    float rd[4];
    rd[0] = fsqrt_approx(N * e2.x * e2.x - e1.x * e1.x);
    rd[1] = fsqrt_approx(N * e2.y * e2.y - e1.y * e1.y);
    rd[2] = fsqrt_approx(N * e2.z * e2.z - e1.z * e1.z);
    rd[3] = fsqrt_approx(N * e2.w * e2.w - e1.w * e1.w);

    float mn = fminf(fminf(rd[0], rd[1]), fminf(rd[2], rd[3]));
#pragma unroll
    for (int off = 16; off; off >>= 1)
        mn = fminf(mn, __shfl_xor_sync(0xffffffffu, mn, off));

    __shared__ float sm[4];
    __shared__ float ss[4];
    if (lane == 0) sm[wid] = mn;
    __syncthreads();
    mn = fminf(fminf(sm[0], sm[1]), fminf(sm[2], sm[3]));

    float e[4], lsum = 0.f;
#pragma unroll
    for (int i = 0; i < 4; i++) { e[i] = __expf(mn - rd[i]); lsum += e[i]; }
#pragma unroll
    for (int off = 16; off; off >>= 1)
        lsum += __shfl_xor_sync(0xffffffffu, lsum, off);
    if (lane == 0) ss[wid] = lsum;
    __syncthreads();
    const float inv = 1.0f / (ss[0] + ss[1] + ss[2] + ss[3]);

    const float4 p = *reinterpret_cast<const float4*>(protos + c * Dn + t * 4);
    const float pv[4] = {p.x, p.y, p.z, p.w};
    float4 wv, wpv;
    float* wvp = &wv.x; float* wppv = &wpv.x;
    float csum = 0.f;
#pragma unroll
    for (int i = 0; i < 4; i++) {
        float w = e[i] * inv;
        wvp[i]  = w;
        wppv[i] = -2.0f * w * pv[i];
        csum += w * pv[i] * pv[i];
    }
    *reinterpret_cast<float4*>(g_W  + c * Dn + t * 4) = wv;
    *reinterpret_cast<float4*>(g_WP + c * Dn + t * 4) = wpv;

#pragma unroll
    for (int off = 16; off; off >>= 1)
        csum += __shfl_xor_sync(0xffffffffu, csum, off);
    __syncthreads();
    if (lane == 0) ss[wid] = csum;
    __syncthreads();
    if (t == 0) g_Cc[c] = ss[0] + ss[1] + ss[2] + ss[3];
}

// ---------------------------------------------------------------------------
// Kernel 2: dual GEMM, packed-operand f32x2 scheme.
//   acc.lo += x^2 * w ;  acc.hi += x * wp   (one fma2 per output element per k)
//   simiP[z][b,c] = lo + hi
// 128x128 tile, BK=16, 256 threads, 8x8 microtile (4 segs x 2 per dim).
// ---------------------------------------------------------------------------
#define BM 128
#define BN 128
#define BK 16
#define LDA 260   // floats per kk row of packed arrays (2*128 padded, 16B-mult)

__global__ __launch_bounds__(256, 1) void gemm_kernel(const float* __restrict__ x) {
    // Packed smem: A[kk][2*row] = x^2, [2*row+1] = x ; B[kk][2*col] = w, wp
    __shared__ float As[BK * LDA];
    __shared__ float Bs[BK * LDA];

    const int tx = threadIdx.x & 15;   // c microtile group
    const int ty = threadIdx.x >> 4;   // b microtile group
    const int c0 = blockIdx.x * BN;    // padded scratch: no bounds check on loads
    const int b0 = blockIdx.y * BM;
    const int kbase = blockIdx.z * (Dn / ZS);

    const int row  = threadIdx.x >> 1; // 0..127 (stages b-row & c-row)
    const int half = threadIdx.x & 1;  // which 8 of the 16 kk's

    const float* xp  = x    + (b0 + row) * Dn + kbase + half * 8;
    const float* wp  = g_W  + (c0 + row) * Dn + kbase + half * 8;
    const float* wpp = g_WP + (c0 + row) * Dn + kbase + half * 8;

    float4 cx[2], cw[2], cwp[2];
    cx[0]  = *reinterpret_cast<const float4*>(xp);
    cx[1]  = *reinterpret_cast<const float4*>(xp + 4);
    cw[0]  = *reinterpret_cast<const float4*>(wp);
    cw[1]  = *reinterpret_cast<const float4*>(wp + 4);
    cwp[0] = *reinterpret_cast<const float4*>(wpp);
    cwp[1] = *reinterpret_cast<const float4*>(wpp + 4);

    unsigned long long acc[8][8];   // [i][j]: lo = sum x^2 w, hi = sum x wp
#pragma unroll
    for (int i = 0; i < 8; i++)
#pragma unroll
        for (int j = 0; j < 8; j++) acc[i][j] = 0ull;

    const int NT = (Dn / ZS) / BK;  // 8 k-tiles
    for (int kt = 0; kt < NT; kt++) {
        // stage packed tiles
        const float* xv  = &cx[0].x;
        const float* wv  = &cw[0].x;
        const float* wpv = &cwp[0].x;
#pragma unroll
        for (int i = 0; i < 8; i++) {
            const int kk = half * 8 + i;
            float xs = xv[i];
            As[kk * LDA + 2 * row]     = xs * xs;
            As[kk * LDA + 2 * row + 1] = xs;
            Bs[kk * LDA + 2 * row]     = wv[i];
            Bs[kk * LDA + 2 * row + 1] = wpv[i];
        }
        __syncthreads();

        if (kt + 1 < NT) {
            const int koff = (kt + 1) * BK;
            cx[0]  = *reinterpret_cast<const float4*>(xp + koff);
            cx[1]  = *reinterpret_cast<const float4*>(xp + koff + 4);
            cw[0]  = *reinterpret_cast<const float4*>(wp + koff);
            cw[1]  = *reinterpret_cast<const float4*>(wp + koff + 4);
            cwp[0] = *reinterpret_cast<const float4*>(wpp + koff);
            cwp[1] = *reinterpret_cast<const float4*>(wpp + koff + 4);
        }

#pragma unroll
        for (int kk = 0; kk < BK; kk++) {
            // A frags: 4 segments x 2 packed (x^2,x) values
            ulonglong2 af[4], bf[4];
#pragma unroll
            for (int s = 0; s < 4; s++) {
                af[s] = *reinterpret_cast<const ulonglong2*>(
                    &As[kk * LDA + 2 * (s * 32 + ty * 2)]);
                bf[s] = *reinterpret_cast<const ulonglong2*>(
                    &Bs[kk * LDA + 2 * (s * 32 + tx * 2)]);
            }
#pragma unroll
            for (int si = 0; si < 4; si++) {
#pragma unroll
                for (int sj = 0; sj < 4; sj++) {
                    fma2(acc[si * 2 + 0][sj * 2 + 0], af[si].x, bf[sj].x);
                    fma2(acc[si * 2 + 0][sj * 2 + 1], af[si].x, bf[sj].y);
                    fma2(acc[si * 2 + 1][sj * 2 + 0], af[si].y, bf[sj].x);
                    fma2(acc[si * 2 + 1][sj * 2 + 1], af[si].y, bf[sj].y);
                }
            }
        }
        __syncthreads();
    }

    float* outz = g_simiP + blockIdx.z * (Bn * Cn);
#pragma unroll
    for (int si = 0; si < 4; si++) {
#pragma unroll
        for (int ii = 0; ii < 2; ii++) {
            const int b = b0 + si * 32 + ty * 2 + ii;
#pragma unroll
            for (int sj = 0; sj < 4; sj++) {
                const int c = c0 + sj * 32 + tx * 2;  // even
                if (c < Cn) {
                    const unsigned long long a0 = acc[si * 2 + ii][sj * 2 + 0];
                    const unsigned long long a1 = acc[si * 2 + ii][sj * 2 + 1];
                    float2 r;
                    r.x = lo32(a0) + hi32(a0);
                    r.y = lo32(a1) + hi32(a1);
                    *reinterpret_cast<float2*>(&outz[b * Cn + c]) = r;
                }
            }
        }
    }
}

// ---------------------------------------------------------------------------
// Kernel 3: one WARP per row; sums ZS K-split partials + Cc, register top-10.
// Output: out[0..B) = predict (float labels), out[B + b*K + k] = conf.
// ---------------------------------------------------------------------------
__global__ void topk_kernel(const int* __restrict__ proto_label,
                            float* __restrict__ out) {
    const int warp = threadIdx.x >> 5;
    const int lane = threadIdx.x & 31;
    const int r = blockIdx.x * 8 + warp;
    if (r >= Bn) return;

    float tv[Kn]; int tix[Kn];
#pragma unroll
    for (int i = 0; i < Kn; i++) { tv[i] = INFINITY; tix[i] = 0x7fffffff; }

    const float* s0 = g_simiP + r * Cn;
    for (int c = lane; c < Cn; c += 32) {
        float v = (s0[c] + s0[Bn * Cn + c]) +
                  (s0[2 * Bn * Cn + c] + s0[3 * Bn * Cn + c]) + g_Cc[c];
        if (v < tv[Kn - 1]) {
            float cv = v; int ci = c;
#pragma unroll
            for (int i = 0; i < Kn; i++) {
                if (cv < tv[i]) {
                    float fv = tv[i]; tv[i] = cv; cv = fv;
                    int   fi = tix[i]; tix[i] = ci; ci = fi;
                }
            }
        }
    }

    float sel_v[Kn]; int sel_i[Kn];
#pragma unroll
    for (int k = 0; k < Kn; k++) {
        float v = tv[0]; int idx = tix[0];
#pragma unroll
        for (int off = 16; off; off >>= 1) {
            float ov = __shfl_down_sync(0xffffffffu, v, off);
            int   oi = __shfl_down_sync(0xffffffffu, idx, off);
            if (ov < v || (ov == v && oi < idx)) { v = ov; idx = oi; }
        }
        v   = __shfl_sync(0xffffffffu, v, 0);
        idx = __shfl_sync(0xffffffffu, idx, 0);
        sel_v[k] = v; sel_i[k] = idx;
        if (tix[0] == idx) {
#pragma unroll
            for (int i = 0; i < Kn - 1; i++) { tv[i] = tv[i + 1]; tix[i] = tix[i + 1]; }
            tv[Kn - 1] = INFINITY; tix[Kn - 1] = 0x7fffffff;
        }
    }

    if (lane == 0) {
        float S = 0.f;
#pragma unroll
        for (int k = 0; k < Kn; k++) S += sel_v[k];
        float bestc = -INFINITY; int bestk = 0;
#pragma unroll
        for (int k = 0; k < Kn; k++) {
            float conf = S / sel_v[k];
            out[Bn + r * Kn + k] = conf;
            if (conf > bestc) { bestc = conf; bestk = k; }
        }
        out[r] = (float)proto_label[sel_i[bestk]];
    }
}

// ---------------------------------------------------------------------------
extern "C" void kernel_launch(void* const* d_in, const int* in_sizes, int n_in,
                              void* d_out, int out_size) {
    const float* x           = (const float*)d_in[0];
    const float* protos      = (const float*)d_in[1];
    const float* ex2         = (const float*)d_in[2];
    const float* ex1         = (const float*)d_in[3];
    const int*   cls_num     = (const int*)d_in[4];
    const int*   proto_label = (const int*)d_in[5];
    float* out = (float*)d_out;

    prep_kernel<<<Cn, 128>>>(protos, ex2, ex1, cls_num);
    dim3 grid(CP / BN, Bn / BM, ZS);   // 8 x 4 x 4 = 128 blocks (one wave)
    gemm_kernel<<<grid, 256>>>(x);
    topk_kernel<<<Bn / 8, 256>>>(proto_label, out);
}

// round 6
// speedup vs baseline: 2.6769x; 1.3095x over previous
#include <cuda_runtime.h>
#include <cuda_bf16.h>
#include <math.h>
#include <stdint.h>

#define Bn 512
#define Cn 1000
#define CP 1024
#define Dn 512
#define Kn 10
#define ZS 4                 // K-split factor
#define KEXT 3072
#define KL (KEXT / ZS)       // 768 per split
#define BKC 64               // K-chunk (bf16 elems)
#define NCH (KL / BKC)       // 12 chunks
#define TM 128
#define TN 128
#define ASTAGE (TM * BKC * 2)   // 16384 B
#define BSTAGE (TN * BKC * 2)   // 16384 B

// Scratch (device globals — zero-initialized, no allocations allowed)
__device__ __nv_bfloat16 g_Aext[Bn * KEXT];   // [b][3072]
__device__ __nv_bfloat16 g_Bext[CP * KEXT];   // [c][3072] (rows >= Cn stay zero)
__device__ float g_Cc[CP];
__device__ float g_simiP[ZS * Bn * Cn];

// ---------------------------------------------------------------------------
// helpers
// ---------------------------------------------------------------------------
__device__ __forceinline__ float fsqrt_approx(float v) {
    float r; asm("sqrt.approx.f32 %0, %1;" : "=f"(r) : "f"(v)); return r;
}
__device__ __forceinline__ void bsplit(float a, __nv_bfloat16& h, __nv_bfloat16& l) {
    h = __float2bfloat16(a);
    l = __float2bfloat16(a - __bfloat162float(h));
}
__device__ __forceinline__ void st4b(__nv_bfloat16* dst,
                                     __nv_bfloat16 a, __nv_bfloat16 b,
                                     __nv_bfloat16 c, __nv_bfloat16 d) {
    __nv_bfloat162 p0 = __halves2bfloat162(a, b);
    __nv_bfloat162 p1 = __halves2bfloat162(c, d);
    uint2 u;
    u.x = *reinterpret_cast<unsigned*>(&p0);
    u.y = *reinterpret_cast<unsigned*>(&p1);
    *reinterpret_cast<uint2*>(dst) = u;
}
__device__ __forceinline__ uint32_t smem_u32(const void* p) {
    uint32_t a;
    asm("{ .reg .u64 t; cvta.to.shared.u64 t, %1; cvt.u32.u64 %0, t; }"
        : "=r"(a) : "l"(p));
    return a;
}

#define LDSM4(r0, r1, r2, r3, addr)                                            \
    asm volatile("ldmatrix.sync.aligned.m8n8.x4.shared.b16 {%0,%1,%2,%3}, [%4];" \
                 : "=r"(r0), "=r"(r1), "=r"(r2), "=r"(r3) : "r"(addr))

#define MMA16816(d, a0, a1, a2, a3, b0, b1)                                    \
    asm volatile("mma.sync.aligned.m16n8k16.row.col.f32.bf16.bf16.f32 "        \
                 "{%0,%1,%2,%3}, {%4,%5,%6,%7}, {%8,%9}, {%0,%1,%2,%3};"       \
                 : "+f"(d[0]), "+f"(d[1]), "+f"(d[2]), "+f"(d[3])              \
                 : "r"(a0), "r"(a1), "r"(a2), "r"(a3), "r"(b0), "r"(b1))

// ---------------------------------------------------------------------------
// Kernel 1: prep — per-class softmax weights, bf16 split, write B_ext + Cc
// B_ext row layout (3072): [hi(w)|hi(wp)|lo(w)|lo(wp)|hi(w)|hi(wp)] (512 each)
// A_ext row layout:        [hi(x2)|hi(x)|hi(x2)|hi(x)|lo(x2)|lo(x)]
// => sum over 3072 = hi.hi + lo.hi + hi.lo  (lo.lo dropped)
// ---------------------------------------------------------------------------
__global__ void prep_kernel(const float* __restrict__ protos,
                            const float* __restrict__ ex2,
                            const float* __restrict__ ex1,
                            const int*   __restrict__ cls_num) {
    const int c = blockIdx.x;
    const int t = threadIdx.x;          // 128
    const int wid = t >> 5, lane = t & 31;
    const float N = (float)cls_num[c];

    const float4 e2 = *reinterpret_cast<const float4*>(ex2 + c * Dn + t * 4);
    const float4 e1 = *reinterpret_cast<const float4*>(ex1 + c * Dn + t * 4);

    float rd[4];
    rd[0] = fsqrt_approx(N * e2.x * e2.x - e1.x * e1.x);
    rd[1] = fsqrt_approx(N * e2.y * e2.y - e1.y * e1.y);
    rd[2] = fsqrt_approx(N * e2.z * e2.z - e1.z * e1.z);
    rd[3] = fsqrt_approx(N * e2.w * e2.w - e1.w * e1.w);

    float mn = fminf(fminf(rd[0], rd[1]), fminf(rd[2], rd[3]));
#pragma unroll
    for (int off = 16; off; off >>= 1)
        mn = fminf(mn, __shfl_xor_sync(0xffffffffu, mn, off));

    __shared__ float sm[4];
    __shared__ float ss[4];
    if (lane == 0) sm[wid] = mn;
    __syncthreads();
    mn = fminf(fminf(sm[0], sm[1]), fminf(sm[2], sm[3]));

    float e[4], lsum = 0.f;
#pragma unroll
    for (int i = 0; i < 4; i++) { e[i] = __expf(mn - rd[i]); lsum += e[i]; }
#pragma unroll
    for (int off = 16; off; off >>= 1)
        lsum += __shfl_xor_sync(0xffffffffu, lsum, off);
    if (lane == 0) ss[wid] = lsum;
    __syncthreads();
    const float inv = 1.0f / (ss[0] + ss[1] + ss[2] + ss[3]);

    const float4 p = *reinterpret_cast<const float4*>(protos + c * Dn + t * 4);
    const float pv[4] = {p.x, p.y, p.z, p.w};
    __nv_bfloat16 wh[4], wl[4], ph[4], pl[4];
    float csum = 0.f;
#pragma unroll
    for (int i = 0; i < 4; i++) {
        float w  = e[i] * inv;
        float wp = -2.0f * w * pv[i];
        bsplit(w,  wh[i], wl[i]);
        bsplit(wp, ph[i], pl[i]);
        csum += w * pv[i] * pv[i];
    }
    __nv_bfloat16* brow = g_Bext + (size_t)c * KEXT + t * 4;
    st4b(brow + 0,    wh[0], wh[1], wh[2], wh[3]);
    st4b(brow + 512,  ph[0], ph[1], ph[2], ph[3]);
    st4b(brow + 1024, wl[0], wl[1], wl[2], wl[3]);
    st4b(brow + 1536, pl[0], pl[1], pl[2], pl[3]);
    st4b(brow + 2048, wh[0], wh[1], wh[2], wh[3]);
    st4b(brow + 2560, ph[0], ph[1], ph[2], ph[3]);

#pragma unroll
    for (int off = 16; off; off >>= 1)
        csum += __shfl_xor_sync(0xffffffffu, csum, off);
    __syncthreads();
    if (lane == 0) ss[wid] = csum;
    __syncthreads();
    if (t == 0) g_Cc[c] = ss[0] + ss[1] + ss[2] + ss[3];
}

// ---------------------------------------------------------------------------
// Kernel 1b: pack x into A_ext (split bf16)
// ---------------------------------------------------------------------------
__global__ void packx_kernel(const float* __restrict__ x) {
    const int b = blockIdx.x;
    const int t = threadIdx.x;
    const float4 xv = *reinterpret_cast<const float4*>(x + b * Dn + t * 4);
    const float xs[4] = {xv.x, xv.y, xv.z, xv.w};
    __nv_bfloat16 x2h[4], x2l[4], xh[4], xl[4];
#pragma unroll
    for (int i = 0; i < 4; i++) {
        bsplit(xs[i] * xs[i], x2h[i], x2l[i]);
        bsplit(xs[i],         xh[i],  xl[i]);
    }
    __nv_bfloat16* arow = g_Aext + (size_t)b * KEXT + t * 4;
    st4b(arow + 0,    x2h[0], x2h[1], x2h[2], x2h[3]);
    st4b(arow + 512,  xh[0],  xh[1],  xh[2],  xh[3]);
    st4b(arow + 1024, x2h[0], x2h[1], x2h[2], x2h[3]);
    st4b(arow + 1536, xh[0],  xh[1],  xh[2],  xh[3]);
    st4b(arow + 2048, x2l[0], x2l[1], x2l[2], x2l[3]);
    st4b(arow + 2560, xl[0],  xl[1],  xl[2],  xl[3]);
}

// ---------------------------------------------------------------------------
// Kernel 2: HMMA bf16 GEMM (mma.sync m16n8k16), 128x128 CTA tile, K-split x4.
// SW128-swizzled smem (128B rows), cp.async double buffering.
// ---------------------------------------------------------------------------
__global__ void __launch_bounds__(256, 1) gemm_kernel() {
    extern __shared__ char dsm[];
    const uint32_t sbase = smem_u32(dsm);          // 1024-aligned by launch cfg
    const uint32_t aS = (sbase + 1023) & ~1023u;
    const uint32_t bS = aS + 2 * ASTAGE;

    const int tid  = threadIdx.x;
    const int lane = tid & 31;
    const int w    = tid >> 5;                     // 0..7
    const int wrow = w >> 2;                       // 0..1 (M)
    const int wcol = w & 3;                        // 0..3 (N)
    const int c0 = blockIdx.x * TN;
    const int b0 = blockIdx.y * TM;
    const int z  = blockIdx.z;
    const int kbase = z * KL;

    // ---- per-lane ldmatrix address components ----
    // A: 4 m16 tiles; lanes 0-15 rows m0..15 (k lo 16B), lanes 16-31 same rows (k hi 16B)
    uint32_t aAddr[4];
    {
        const int sel = (lane >> 4) * 16;          // byte offset within 32B k16
#pragma unroll
        for (int mt = 0; mt < 4; mt++) {
            const int row = wrow * 64 + mt * 16 + (lane & 15);
            aAddr[mt] = row * 128 + (((row & 7) * 16) ^ sel);  // xor folded; kk adds ^-free 32B steps
        }
    }
    // B: 2 ldmatrix.x4, each covers 2 n8 tiles (16 n rows x k16)
    uint32_t bAddr[2];
    {
        const int sel = ((lane >> 3) & 1) * 16;
#pragma unroll
        for (int np = 0; np < 2; np++) {
            const int row = wcol * 32 + np * 16 + (lane & 7) + ((lane >> 4) << 3);
            bAddr[np] = row * 128 + (((row & 7) * 16) ^ sel);
        }
    }
    // NOTE: swizzle SWZ(row*128 + off) = row*128 + (off ^ ((row&7)*16)); since the
    // kk step (32B) and the 16B sel both live in off, and xor with (row&7)*16 only
    // touches bits 4-6, adding kk*32 AFTER xor is wrong when kk*32 collides with the
    // xor bits. kk*32 has bits >=5; xor mask is 0x70 (bits 4..6) — they overlap.
    // So compute full xor per use instead:
#define A_ADDR(mt, kk)  (aS + bufA + ((aAddr[mt] & ~0x7Fu) | ((((aAddr[mt]) & 0x7Fu) ^ 0u) ^ 0u), 0u)
    // (macro above unused — addresses computed inline below)

    // ---- cp.async staging ----
#define LOAD_CHUNK(ci, pp) do {                                                     \
    const int _koff = kbase + (ci) * BKC;                                           \
    _Pragma("unroll")                                                               \
    for (int _t = 0; _t < 4; _t++) {                                                \
        const int _idx = tid + _t * 256;             /* 0..1023 */                  \
        const int _row = _idx >> 3, _seg = _idx & 7;                                \
        const __nv_bfloat16* _srcA =                                                \
            g_Aext + (size_t)(b0 + _row) * KEXT + _koff + _seg * 8;                 \
        const uint32_t _dA = aS + (pp) * ASTAGE + _row * 128 +                      \
                             ((_seg * 16) ^ ((_row & 7) * 16));                     \
        asm volatile("cp.async.cg.shared.global [%0], [%1], 16;"                    \
                     :: "r"(_dA), "l"(_srcA) : "memory");                           \
        const __nv_bfloat16* _srcB =                                                \
            g_Bext + (size_t)(c0 + _row) * KEXT + _koff + _seg * 8;                 \
        const uint32_t _dB = bS + (pp) * BSTAGE + _row * 128 +                      \
                             ((_seg * 16) ^ ((_row & 7) * 16));                     \
        asm volatile("cp.async.cg.shared.global [%0], [%1], 16;"                    \
                     :: "r"(_dB), "l"(_srcB) : "memory");                           \
    }                                                                               \
    asm volatile("cp.async.commit_group;" ::: "memory");                            \
} while (0)

    float acc[4][4][4];
#pragma unroll
    for (int i = 0; i < 4; i++)
#pragma unroll
        for (int j = 0; j < 4; j++)
#pragma unroll
            for (int r = 0; r < 4; r++) acc[i][j][r] = 0.f;

    LOAD_CHUNK(0, 0);

    for (int i = 0; i < NCH; i++) {
        const int p = i & 1;
        if (i + 1 < NCH) {
            LOAD_CHUNK(i + 1, p ^ 1);
            asm volatile("cp.async.wait_group 1;" ::: "memory");
        } else {
            asm volatile("cp.async.wait_group 0;" ::: "memory");
        }
        __syncthreads();

        const uint32_t aB = aS + p * ASTAGE;
        const uint32_t bB = bS + p * BSTAGE;
#pragma unroll
        for (int kk = 0; kk < BKC / 16; kk++) {     // 4 k16 steps
            const uint32_t ko = kk * 32;            // byte offset of k16 within row
            uint32_t af[4][4], bf[2][4];
#pragma unroll
            for (int mt = 0; mt < 4; mt++) {
                // recompose: base rowterm + ((ko + sel) ^ xorv); aAddr holds rowterm + (xorv ^ sel)
                // Safe recomputation: extract row parts.
                const uint32_t rowterm = aAddr[mt] & ~0x7Fu;
                const uint32_t mix     = aAddr[mt] & 0x7Fu;       // (xorv ^ sel)
                const uint32_t addr    = aB + rowterm + (mix ^ ko);
                LDSM4(af[mt][0], af[mt][1], af[mt][2], af[mt][3], addr);
            }
#pragma unroll
            for (int np = 0; np < 2; np++) {
                const uint32_t rowterm = bAddr[np] & ~0x7Fu;
                const uint32_t mix     = bAddr[np] & 0x7Fu;
                const uint32_t addr    = bB + rowterm + (mix ^ ko);
                LDSM4(bf[np][0], bf[np][1], bf[np][2], bf[np][3], addr);
            }
#pragma unroll
            for (int mt = 0; mt < 4; mt++) {
#pragma unroll
                for (int np = 0; np < 2; np++) {
                    MMA16816(acc[mt][np * 2 + 0],
                             af[mt][0], af[mt][1], af[mt][2], af[mt][3],
                             bf[np][0], bf[np][1]);
                    MMA16816(acc[mt][np * 2 + 1],
                             af[mt][0], af[mt][1], af[mt][2], af[mt][3],
                             bf[np][2], bf[np][3]);
                }
            }
        }
        __syncthreads();
    }

    // ---- epilogue: write fp32 partials ----
    float* basez = g_simiP + (size_t)z * (Bn * Cn);
#pragma unroll
    for (int mt = 0; mt < 4; mt++) {
        const int m = b0 + wrow * 64 + mt * 16 + (lane >> 2);
#pragma unroll
        for (int nt = 0; nt < 4; nt++) {
            const int n = c0 + wcol * 32 + nt * 8 + (lane & 3) * 2;
            if (n < Cn) {
                float2 v0 = make_float2(acc[mt][nt][0], acc[mt][nt][1]);
                float2 v1 = make_float2(acc[mt][nt][2], acc[mt][nt][3]);
                *reinterpret_cast<float2*>(basez + (size_t)m * Cn + n) = v0;
                *reinterpret_cast<float2*>(basez + (size_t)(m + 8) * Cn + n) = v1;
            }
        }
    }
#undef LOAD_CHUNK
}

// ---------------------------------------------------------------------------
// Kernel 3: one WARP per row; sums ZS partials + Cc, register top-10.
// ---------------------------------------------------------------------------
__global__ void topk_kernel(const int* __restrict__ proto_label,
                            float* __restrict__ out) {
    const int warp = threadIdx.x >> 5;
    const int lane = threadIdx.x & 31;
    const int r = blockIdx.x * 8 + warp;
    if (r >= Bn) return;

    float tv[Kn]; int tix[Kn];
#pragma unroll
    for (int i = 0; i < Kn; i++) { tv[i] = INFINITY; tix[i] = 0x7fffffff; }

    const float* s0 = g_simiP + (size_t)r * Cn;
    for (int c = lane; c < Cn; c += 32) {
        float v = (s0[c] + s0[(size_t)Bn * Cn + c]) +
                  (s0[2 * (size_t)Bn * Cn + c] + s0[3 * (size_t)Bn * Cn + c]) +
                  g_Cc[c];
        if (v < tv[Kn - 1]) {
            float cv = v; int ci = c;
#pragma unroll
            for (int i = 0; i < Kn; i++) {
                if (cv < tv[i]) {
                    float fv = tv[i]; tv[i] = cv; cv = fv;
                    int   fi = tix[i]; tix[i] = ci; ci = fi;
                }
            }
        }
    }

    float sel_v[Kn]; int sel_i[Kn];
#pragma unroll
    for (int k = 0; k < Kn; k++) {
        float v = tv[0]; int idx = tix[0];
#pragma unroll
        for (int off = 16; off; off >>= 1) {
            float ov = __shfl_down_sync(0xffffffffu, v, off);
            int   oi = __shfl_down_sync(0xffffffffu, idx, off);
            if (ov < v || (ov == v && oi < idx)) { v = ov; idx = oi; }
        }
        v   = __shfl_sync(0xffffffffu, v, 0);
        idx = __shfl_sync(0xffffffffu, idx, 0);
        sel_v[k] = v; sel_i[k] = idx;
        if (tix[0] == idx) {
#pragma unroll
            for (int i = 0; i < Kn - 1; i++) { tv[i] = tv[i + 1]; tix[i] = tix[i + 1]; }
            tv[Kn - 1] = INFINITY; tix[Kn - 1] = 0x7fffffff;
        }
    }

    if (lane == 0) {
        float S = 0.f;
#pragma unroll
        for (int k = 0; k < Kn; k++) S += sel_v[k];
        float bestc = -INFINITY; int bestk = 0;
#pragma unroll
        for (int k = 0; k < Kn; k++) {
            float conf = S / sel_v[k];
            out[Bn + r * Kn + k] = conf;
            if (conf > bestc) { bestc = conf; bestk = k; }
        }
        out[r] = (float)proto_label[sel_i[bestk]];
    }
}

// ---------------------------------------------------------------------------
extern "C" void kernel_launch(void* const* d_in, const int* in_sizes, int n_in,
                              void* d_out, int out_size) {
    const float* x           = (const float*)d_in[0];
    const float* protos      = (const float*)d_in[1];
    const float* ex2         = (const float*)d_in[2];
    const float* ex1         = (const float*)d_in[3];
    const int*   cls_num     = (const int*)d_in[4];
    const int*   proto_label = (const int*)d_in[5];
    float* out = (float*)d_out;

    const int smem_sz = 2 * ASTAGE + 2 * BSTAGE + 1024;  // 66560 B
    static int attr_done = 0;
    if (!attr_done) {
        cudaFuncSetAttribute(gemm_kernel,
                             cudaFuncAttributeMaxDynamicSharedMemorySize, smem_sz);
        attr_done = 1;
    }

    packx_kernel<<<Bn, 128>>>(x);
    prep_kernel<<<Cn, 128>>>(protos, ex2, ex1, cls_num);
    dim3 grid(CP / TN, Bn / TM, ZS);   // 8 x 4 x 4 = 128 CTAs
    gemm_kernel<<<grid, 256, smem_sz>>>();
    topk_kernel<<<Bn / 8, 256>>>(proto_label, out);
}

// round 7
// speedup vs baseline: 3.4555x; 1.2909x over previous
#include <cuda_runtime.h>
#include <cuda_bf16.h>
#include <math.h>
#include <stdint.h>

#define Bn 512
#define Cn 1000
#define CP 1024
#define Dn 512
#define Kn 10
#define ZS 4                 // K-split factor
#define KEXT 3072
#define KL (KEXT / ZS)       // 768 per split
#define BKC 64               // K-chunk (bf16 elems)
#define NCH (KL / BKC)       // 12 chunks
#define TM 128
#define TN 128
#define ASTAGE (TM * BKC * 2)   // 16384 B
#define BSTAGE (TN * BKC * 2)   // 16384 B

// Scratch (device globals — zero-initialized, no allocations allowed)
__device__ __nv_bfloat16 g_Aext[Bn * KEXT];   // [b][3072]
__device__ __nv_bfloat16 g_Bext[CP * KEXT];   // [c][3072] (rows >= Cn stay zero)
__device__ float g_Cc[CP];
__device__ float g_simiP[ZS * Bn * Cn];

// ---------------------------------------------------------------------------
// helpers
// ---------------------------------------------------------------------------
__device__ __forceinline__ float fsqrt_approx(float v) {
    float r; asm("sqrt.approx.f32 %0, %1;" : "=f"(r) : "f"(v)); return r;
}
__device__ __forceinline__ void bsplit(float a, __nv_bfloat16& h, __nv_bfloat16& l) {
    h = __float2bfloat16(a);
    l = __float2bfloat16(a - __bfloat162float(h));
}
__device__ __forceinline__ void st4b(__nv_bfloat16* dst,
                                     __nv_bfloat16 a, __nv_bfloat16 b,
                                     __nv_bfloat16 c, __nv_bfloat16 d) {
    __nv_bfloat162 p0 = __halves2bfloat162(a, b);
    __nv_bfloat162 p1 = __halves2bfloat162(c, d);
    uint2 u;
    u.x = *reinterpret_cast<unsigned*>(&p0);
    u.y = *reinterpret_cast<unsigned*>(&p1);
    *reinterpret_cast<uint2*>(dst) = u;
}
__device__ __forceinline__ uint32_t smem_u32(const void* p) {
    uint32_t a;
    asm("{ .reg .u64 t; cvta.to.shared.u64 t, %1; cvt.u32.u64 %0, t; }"
        : "=r"(a) : "l"(p));
    return a;
}

#define LDSM4(r0, r1, r2, r3, addr)                                            \
    asm volatile("ldmatrix.sync.aligned.m8n8.x4.shared.b16 {%0,%1,%2,%3}, [%4];" \
                 : "=r"(r0), "=r"(r1), "=r"(r2), "=r"(r3) : "r"(addr))

#define MMA16816(d, a0, a1, a2, a3, b0, b1)                                    \
    asm volatile("mma.sync.aligned.m16n8k16.row.col.f32.bf16.bf16.f32 "        \
                 "{%0,%1,%2,%3}, {%4,%5,%6,%7}, {%8,%9}, {%0,%1,%2,%3};"       \
                 : "+f"(d[0]), "+f"(d[1]), "+f"(d[2]), "+f"(d[3])              \
                 : "r"(a0), "r"(a1), "r"(a2), "r"(a3), "r"(b0), "r"(b1))

// ---------------------------------------------------------------------------
// Kernel 1 (fused): blocks [0, Bn) pack x -> A_ext; blocks [Bn, Bn+Cn) do
// per-class softmax prep -> B_ext + Cc. 128 threads each.
// A_ext row layout (3072): [hi(x2)|hi(x)|hi(x2)|hi(x)|lo(x2)|lo(x)]
// B_ext row layout (3072): [hi(w)|hi(wp)|lo(w)|lo(wp)|hi(w)|hi(wp)]
// => dot over 3072 = hi.hi + lo.hi + hi.lo  (lo.lo dropped, ~2^-17 rel)
// ---------------------------------------------------------------------------
__global__ void prep_kernel(const float* __restrict__ x,
                            const float* __restrict__ protos,
                            const float* __restrict__ ex2,
                            const float* __restrict__ ex1,
                            const int*   __restrict__ cls_num) {
    const int t = threadIdx.x;          // 128

    if (blockIdx.x < Bn) {
        // ---- packx role ----
        const int b = blockIdx.x;
        const float4 xv = *reinterpret_cast<const float4*>(x + b * Dn + t * 4);
        const float xs[4] = {xv.x, xv.y, xv.z, xv.w};
        __nv_bfloat16 x2h[4], x2l[4], xh[4], xl[4];
#pragma unroll
        for (int i = 0; i < 4; i++) {
            bsplit(xs[i] * xs[i], x2h[i], x2l[i]);
            bsplit(xs[i],         xh[i],  xl[i]);
        }
        __nv_bfloat16* arow = g_Aext + (size_t)b * KEXT + t * 4;
        st4b(arow + 0,    x2h[0], x2h[1], x2h[2], x2h[3]);
        st4b(arow + 512,  xh[0],  xh[1],  xh[2],  xh[3]);
        st4b(arow + 1024, x2h[0], x2h[1], x2h[2], x2h[3]);
        st4b(arow + 1536, xh[0],  xh[1],  xh[2],  xh[3]);
        st4b(arow + 2048, x2l[0], x2l[1], x2l[2], x2l[3]);
        st4b(arow + 2560, xl[0],  xl[1],  xl[2],  xl[3]);
        return;
    }

    // ---- prep role ----
    const int c = blockIdx.x - Bn;
    const int wid = t >> 5, lane = t & 31;
    const float N = (float)cls_num[c];

    const float4 e2 = *reinterpret_cast<const float4*>(ex2 + c * Dn + t * 4);
    const float4 e1 = *reinterpret_cast<const float4*>(ex1 + c * Dn + t * 4);

    float rd[4];
    rd[0] = fsqrt_approx(N * e2.x * e2.x - e1.x * e1.x);
    rd[1] = fsqrt_approx(N * e2.y * e2.y - e1.y * e1.y);
    rd[2] = fsqrt_approx(N * e2.z * e2.z - e1.z * e1.z);
    rd[3] = fsqrt_approx(N * e2.w * e2.w - e1.w * e1.w);

    float mn = fminf(fminf(rd[0], rd[1]), fminf(rd[2], rd[3]));
#pragma unroll
    for (int off = 16; off; off >>= 1)
        mn = fminf(mn, __shfl_xor_sync(0xffffffffu, mn, off));

    __shared__ float sm[4];
    __shared__ float ss[4];
    if (lane == 0) sm[wid] = mn;
    __syncthreads();
    mn = fminf(fminf(sm[0], sm[1]), fminf(sm[2], sm[3]));

    float e[4], lsum = 0.f;
#pragma unroll
    for (int i = 0; i < 4; i++) { e[i] = __expf(mn - rd[i]); lsum += e[i]; }
#pragma unroll
    for (int off = 16; off; off >>= 1)
        lsum += __shfl_xor_sync(0xffffffffu, lsum, off);
    if (lane == 0) ss[wid] = lsum;
    __syncthreads();
    const float inv = 1.0f / (ss[0] + ss[1] + ss[2] + ss[3]);

    const float4 p = *reinterpret_cast<const float4*>(protos + c * Dn + t * 4);
    const float pv[4] = {p.x, p.y, p.z, p.w};
    __nv_bfloat16 wh[4], wl[4], ph[4], pl[4];
    float csum = 0.f;
#pragma unroll
    for (int i = 0; i < 4; i++) {
        float w  = e[i] * inv;
        float wp = -2.0f * w * pv[i];
        bsplit(w,  wh[i], wl[i]);
        bsplit(wp, ph[i], pl[i]);
        csum += w * pv[i] * pv[i];
    }
    __nv_bfloat16* brow = g_Bext + (size_t)c * KEXT + t * 4;
    st4b(brow + 0,    wh[0], wh[1], wh[2], wh[3]);
    st4b(brow + 512,  ph[0], ph[1], ph[2], ph[3]);
    st4b(brow + 1024, wl[0], wl[1], wl[2], wl[3]);
    st4b(brow + 1536, pl[0], pl[1], pl[2], pl[3]);
    st4b(brow + 2048, wh[0], wh[1], wh[2], wh[3]);
    st4b(brow + 2560, ph[0], ph[1], ph[2], ph[3]);

#pragma unroll
    for (int off = 16; off; off >>= 1)
        csum += __shfl_xor_sync(0xffffffffu, csum, off);
    __syncthreads();
    if (lane == 0) ss[wid] = csum;
    __syncthreads();
    if (t == 0) g_Cc[c] = ss[0] + ss[1] + ss[2] + ss[3];
}

// ---------------------------------------------------------------------------
// Kernel 2: HMMA bf16 GEMM (mma.sync m16n8k16), 128x128 CTA tile, K-split x4.
// SW128-swizzled smem (128B rows), cp.async double buffering.
// ---------------------------------------------------------------------------
__global__ void __launch_bounds__(256, 1) gemm_kernel() {
    extern __shared__ char dsm[];
    const uint32_t sbase = smem_u32(dsm);
    const uint32_t aS = (sbase + 1023) & ~1023u;
    const uint32_t bS = aS + 2 * ASTAGE;

    const int tid  = threadIdx.x;
    const int lane = tid & 31;
    const int w    = tid >> 5;                     // 0..7
    const int wrow = w >> 2;                       // 0..1 (M)
    const int wcol = w & 3;                        // 0..3 (N)
    const int c0 = blockIdx.x * TN;
    const int b0 = blockIdx.y * TM;
    const int z  = blockIdx.z;
    const int kbase = z * KL;

    uint32_t aAddr[4];
    {
        const int sel = (lane >> 4) * 16;
#pragma unroll
        for (int mt = 0; mt < 4; mt++) {
            const int row = wrow * 64 + mt * 16 + (lane & 15);
            aAddr[mt] = row * 128 + (((row & 7) * 16) ^ sel);
        }
    }
    uint32_t bAddr[2];
    {
        const int sel = ((lane >> 3) & 1) * 16;
#pragma unroll
        for (int np = 0; np < 2; np++) {
            const int row = wcol * 32 + np * 16 + (lane & 7) + ((lane >> 4) << 3);
            bAddr[np] = row * 128 + (((row & 7) * 16) ^ sel);
        }
    }

#define LOAD_CHUNK(ci, pp) do {                                                     \
    const int _koff = kbase + (ci) * BKC;                                           \
    _Pragma("unroll")                                                               \
    for (int _t = 0; _t < 4; _t++) {                                                \
        const int _idx = tid + _t * 256;                                            \
        const int _row = _idx >> 3, _seg = _idx & 7;                                \
        const __nv_bfloat16* _srcA =                                                \
            g_Aext + (size_t)(b0 + _row) * KEXT + _koff + _seg * 8;                 \
        const uint32_t _dA = aS + (pp) * ASTAGE + _row * 128 +                      \
                             ((_seg * 16) ^ ((_row & 7) * 16));                     \
        asm volatile("cp.async.cg.shared.global [%0], [%1], 16;"                    \
                     :: "r"(_dA), "l"(_srcA) : "memory");                           \
        const __nv_bfloat16* _srcB =                                                \
            g_Bext + (size_t)(c0 + _row) * KEXT + _koff + _seg * 8;                 \
        const uint32_t _dB = bS + (pp) * BSTAGE + _row * 128 +                      \
                             ((_seg * 16) ^ ((_row & 7) * 16));                     \
        asm volatile("cp.async.cg.shared.global [%0], [%1], 16;"                    \
                     :: "r"(_dB), "l"(_srcB) : "memory");                           \
    }                                                                               \
    asm volatile("cp.async.commit_group;" ::: "memory");                            \
} while (0)

    float acc[4][4][4];
#pragma unroll
    for (int i = 0; i < 4; i++)
#pragma unroll
        for (int j = 0; j < 4; j++)
#pragma unroll
            for (int r = 0; r < 4; r++) acc[i][j][r] = 0.f;

    LOAD_CHUNK(0, 0);

    for (int i = 0; i < NCH; i++) {
        const int p = i & 1;
        if (i + 1 < NCH) {
            LOAD_CHUNK(i + 1, p ^ 1);
            asm volatile("cp.async.wait_group 1;" ::: "memory");
        } else {
            asm volatile("cp.async.wait_group 0;" ::: "memory");
        }
        __syncthreads();

        const uint32_t aB = aS + p * ASTAGE;
        const uint32_t bB = bS + p * BSTAGE;
#pragma unroll
        for (int kk = 0; kk < BKC / 16; kk++) {
            const uint32_t ko = kk * 32;
            uint32_t af[4][4], bf[2][4];
#pragma unroll
            for (int mt = 0; mt < 4; mt++) {
                const uint32_t rowterm = aAddr[mt] & ~0x7Fu;
                const uint32_t mix     = aAddr[mt] & 0x7Fu;
                const uint32_t addr    = aB + rowterm + (mix ^ ko);
                LDSM4(af[mt][0], af[mt][1], af[mt][2], af[mt][3], addr);
            }
#pragma unroll
            for (int np = 0; np < 2; np++) {
                const uint32_t rowterm = bAddr[np] & ~0x7Fu;
                const uint32_t mix     = bAddr[np] & 0x7Fu;
                const uint32_t addr    = bB + rowterm + (mix ^ ko);
                LDSM4(bf[np][0], bf[np][1], bf[np][2], bf[np][3], addr);
            }
#pragma unroll
            for (int mt = 0; mt < 4; mt++) {
#pragma unroll
                for (int np = 0; np < 2; np++) {
                    MMA16816(acc[mt][np * 2 + 0],
                             af[mt][0], af[mt][1], af[mt][2], af[mt][3],
                             bf[np][0], bf[np][1]);
                    MMA16816(acc[mt][np * 2 + 1],
                             af[mt][0], af[mt][1], af[mt][2], af[mt][3],
                             bf[np][2], bf[np][3]);
                }
            }
        }
        __syncthreads();
    }

    float* basez = g_simiP + (size_t)z * (Bn * Cn);
#pragma unroll
    for (int mt = 0; mt < 4; mt++) {
        const int m = b0 + wrow * 64 + mt * 16 + (lane >> 2);
#pragma unroll
        for (int nt = 0; nt < 4; nt++) {
            const int n = c0 + wcol * 32 + nt * 8 + (lane & 3) * 2;
            if (n < Cn) {
                float2 v0 = make_float2(acc[mt][nt][0], acc[mt][nt][1]);
                float2 v1 = make_float2(acc[mt][nt][2], acc[mt][nt][3]);
                *reinterpret_cast<float2*>(basez + (size_t)m * Cn + n) = v0;
                *reinterpret_cast<float2*>(basez + (size_t)(m + 8) * Cn + n) = v1;
            }
        }
    }
#undef LOAD_CHUNK
}

// ---------------------------------------------------------------------------
// Kernel 3: one BLOCK (4 warps) per row. Each warp: register top-10 over a
// disjoint 250-class range + shuffle-merge to a sorted list. Thread 0 then
// 4-way merges the sorted lists (ranges are index-ordered -> stable ties).
// Output: out[0..B) = predict (float labels), out[B + b*K + k] = conf.
// ---------------------------------------------------------------------------
#define WRANGE 250

__global__ void topk_kernel(const int* __restrict__ proto_label,
                            float* __restrict__ out) {
    const int r    = blockIdx.x;        // row
    const int warp = threadIdx.x >> 5;  // 0..3
    const int lane = threadIdx.x & 31;

    __shared__ float s_v[4][Kn];
    __shared__ int   s_i[4][Kn];

    float tv[Kn]; int tix[Kn];
#pragma unroll
    for (int i = 0; i < Kn; i++) { tv[i] = INFINITY; tix[i] = 0x7fffffff; }

    const float* s0 = g_simiP + (size_t)r * Cn;
    const int cbeg = warp * WRANGE;
    const int cend = cbeg + WRANGE;
    for (int c = cbeg + lane; c < cend; c += 32) {
        float v = (s0[c] + s0[(size_t)Bn * Cn + c]) +
                  (s0[2 * (size_t)Bn * Cn + c] + s0[3 * (size_t)Bn * Cn + c]) +
                  g_Cc[c];
        if (v < tv[Kn - 1]) {
            float cv = v; int ci = c;
#pragma unroll
            for (int i = 0; i < Kn; i++) {
                if (cv < tv[i]) {
                    float fv = tv[i]; tv[i] = cv; cv = fv;
                    int   fi = tix[i]; tix[i] = ci; ci = fi;
                }
            }
        }
    }

    // warp-level merge: 10 rounds of shuffle argmin over lane heads
#pragma unroll
    for (int k = 0; k < Kn; k++) {
        float v = tv[0]; int idx = tix[0];
#pragma unroll
        for (int off = 16; off; off >>= 1) {
            float ov = __shfl_down_sync(0xffffffffu, v, off);
            int   oi = __shfl_down_sync(0xffffffffu, idx, off);
            if (ov < v || (ov == v && oi < idx)) { v = ov; idx = oi; }
        }
        v   = __shfl_sync(0xffffffffu, v, 0);
        idx = __shfl_sync(0xffffffffu, idx, 0);
        if (lane == 0) { s_v[warp][k] = v; s_i[warp][k] = idx; }
        if (tix[0] == idx) {
#pragma unroll
            for (int i = 0; i < Kn - 1; i++) { tv[i] = tv[i + 1]; tix[i] = tix[i + 1]; }
            tv[Kn - 1] = INFINITY; tix[Kn - 1] = 0x7fffffff;
        }
    }
    __syncthreads();

    if (threadIdx.x == 0) {
        // 4-way merge of sorted lists; tie -> lowest warp (lowest index range)
        int ptr[4] = {0, 0, 0, 0};
        float sel_v[Kn]; int sel_i[Kn];
#pragma unroll
        for (int k = 0; k < Kn; k++) {
            float bv = INFINITY; int bw = 0;
#pragma unroll
            for (int wq = 0; wq < 4; wq++) {
                float hv = (ptr[wq] < Kn) ? s_v[wq][ptr[wq]] : INFINITY;
                if (hv < bv) { bv = hv; bw = wq; }
            }
            sel_v[k] = bv;
            sel_i[k] = s_i[bw][ptr[bw]];
            ptr[bw]++;
        }
        float S = 0.f;
#pragma unroll
        for (int k = 0; k < Kn; k++) S += sel_v[k];
        float bestc = -INFINITY; int bestk = 0;
#pragma unroll
        for (int k = 0; k < Kn; k++) {
            float conf = S / sel_v[k];
            out[Bn + r * Kn + k] = conf;
            if (conf > bestc) { bestc = conf; bestk = k; }
        }
        out[r] = (float)proto_label[sel_i[bestk]];
    }
}

// ---------------------------------------------------------------------------
extern "C" void kernel_launch(void* const* d_in, const int* in_sizes, int n_in,
                              void* d_out, int out_size) {
    const float* x           = (const float*)d_in[0];
    const float* protos      = (const float*)d_in[1];
    const float* ex2         = (const float*)d_in[2];
    const float* ex1         = (const float*)d_in[3];
    const int*   cls_num     = (const int*)d_in[4];
    const int*   proto_label = (const int*)d_in[5];
    float* out = (float*)d_out;

    const int smem_sz = 2 * ASTAGE + 2 * BSTAGE + 1024;  // 66560 B
    static int attr_done = 0;
    if (!attr_done) {
        cudaFuncSetAttribute(gemm_kernel,
                             cudaFuncAttributeMaxDynamicSharedMemorySize, smem_sz);
        attr_done = 1;
    }

    prep_kernel<<<Bn + Cn, 128>>>(x, protos, ex2, ex1, cls_num);
    dim3 grid(CP / TN, Bn / TM, ZS);   // 8 x 4 x 4 = 128 CTAs
    gemm_kernel<<<grid, 256, smem_sz>>>();
    topk_kernel<<<Bn, 128>>>(proto_label, out);
}